// round 3
// baseline (speedup 1.0000x reference)
#include <cuda_runtime.h>
#include <cuda_bf16.h>
#include <stdint.h>

// Warp-per-row gather. Lane j: table = j>>3, sub-float4 = j&7.
// Row output = [W0[t0] | W1[t1] | W2[t2] | W3[t3]] (4 x 32 floats = 128).
//
// Index dtype (int64 vs int32) is detected in-kernel: each warp inspects the
// high 32-bit halves of the first 32 words of T. If T is int64 little-endian
// with values < 366, all high halves are zero; if int32, the odd words are
// random indices (dims 366/24/7/60) and P(all 32 zero) ~ 1e-50. One cached
// load + one ballot per warp; no separate detection launch.
__global__ void __launch_bounds__(256)
time_encoder_gather_kernel(const void* __restrict__ Tv,
                           const float4* __restrict__ W0,
                           const float4* __restrict__ W1,
                           const float4* __restrict__ W2,
                           const float4* __restrict__ W3,
                           float4* __restrict__ out,
                           int N) {
    const int lane = threadIdx.x & 31;
    const int dim  = lane >> 3;   // which table (0..3)
    const int sub  = lane & 7;    // which float4 within the 32-float slice

    // --- in-warp dtype detection ---
    const unsigned int* t32 = (const unsigned int*)Tv;
    unsigned int hi = __ldg(&t32[2 * lane + 1]);
    const bool is64 = (__ballot_sync(0xFFFFFFFFu, hi != 0u) == 0u);

    // Per-lane table base pointer (loop-invariant).
    const float4* W = (dim == 0) ? W0 : (dim == 1) ? W1 : (dim == 2) ? W2 : W3;

    const int warp   = (int)((blockIdx.x * blockDim.x + threadIdx.x) >> 5);
    const int nwarps = (int)((gridDim.x * blockDim.x) >> 5);

    const int*       T32 = (const int*)Tv;
    const long long* T64 = (const long long*)Tv;

    if (is64) {
        for (int row = warp; row < N; row += nwarps) {
            int idx = (int)__ldg(&T64[(size_t)row * 4 + dim]);
            float4 v = __ldg(&W[idx * 8 + sub]);      // tables ~57KB: L1-resident
            __stcs(&out[(size_t)row * 32 + lane], v); // write-once: evict-first
        }
    } else {
        for (int row = warp; row < N; row += nwarps) {
            int idx = __ldg(&T32[(size_t)row * 4 + dim]);
            float4 v = __ldg(&W[idx * 8 + sub]);
            __stcs(&out[(size_t)row * 32 + lane], v);
        }
    }
}

extern "C" void kernel_launch(void* const* d_in, const int* in_sizes, int n_in,
                              void* d_out, int out_size) {
    const void*   T  = d_in[0];
    const float4* W0 = (const float4*)d_in[1];
    const float4* W1 = (const float4*)d_in[2];
    const float4* W2 = (const float4*)d_in[3];
    const float4* W3 = (const float4*)d_in[4];
    float4* out = (float4*)d_out;

    const int N = in_sizes[0] / 4;  // T has N*4 index elements

    // Single persistent wave: 8 resident blocks/SM (256 thr, 32 regs) x 148 SMs.
    const int threads = 256;
    const int blocks  = 148 * 8;
    time_encoder_gather_kernel<<<blocks, threads>>>(T, W0, W1, W2, W3, out, N);
}

// round 4
// speedup vs baseline: 1.0838x; 1.0838x over previous
#include <cuda_runtime.h>
#include <cuda_bf16.h>
#include <stdint.h>

// Warp-per-row gather. Lane j: table = j>>3, sub-float4 = j&7.
// Row output = [W0[t0] | W1[t1] | W2[t2] | W3[t3]] (4 x 32 floats = 128).
//
// Index dtype (int64 vs int32) detected in-kernel: each warp inspects the
// high 32-bit halves of the first 32 words of T. int64 little-endian with
// values < 366 -> all high halves zero; int32 -> odd words are random
// indices, P(all 32 zero) ~ 1e-50. One cached load + one ballot per warp.
__global__ void __launch_bounds__(256)
time_encoder_gather_kernel(const void* __restrict__ Tv,
                           const float4* __restrict__ W0,
                           const float4* __restrict__ W1,
                           const float4* __restrict__ W2,
                           const float4* __restrict__ W3,
                           float4* __restrict__ out,
                           int N) {
    const int lane = threadIdx.x & 31;
    const int dim  = lane >> 3;   // which table (0..3)
    const int sub  = lane & 7;    // which float4 within the 32-float slice

    // --- in-warp dtype detection ---
    const unsigned int* t32 = (const unsigned int*)Tv;
    unsigned int hi = __ldg(&t32[2 * lane + 1]);
    const bool is64 = (__ballot_sync(0xFFFFFFFFu, hi != 0u) == 0u);

    // Per-lane table base pointer (loop-invariant).
    const float4* W = (dim == 0) ? W0 : (dim == 1) ? W1 : (dim == 2) ? W2 : W3;

    const int warp   = (int)((blockIdx.x * blockDim.x + threadIdx.x) >> 5);
    const int nwarps = (int)((gridDim.x * blockDim.x) >> 5);

    const int*       T32 = (const int*)Tv;
    const long long* T64 = (const long long*)Tv;

    if (is64) {
        for (int row = warp; row < N; row += nwarps) {
            int idx = (int)__ldg(&T64[(size_t)row * 4 + dim]);
            float4 v = __ldg(&W[idx * 8 + sub]);      // tables ~57KB: L1-resident
            __stcs(&out[(size_t)row * 32 + lane], v); // write-once: evict-first
        }
    } else {
        for (int row = warp; row < N; row += nwarps) {
            int idx = __ldg(&T32[(size_t)row * 4 + dim]);
            float4 v = __ldg(&W[idx * 8 + sub]);
            __stcs(&out[(size_t)row * 32 + lane], v);
        }
    }
}

extern "C" void kernel_launch(void* const* d_in, const int* in_sizes, int n_in,
                              void* d_out, int out_size) {
    const void*   T  = d_in[0];
    const float4* W0 = (const float4*)d_in[1];
    const float4* W1 = (const float4*)d_in[2];
    const float4* W2 = (const float4*)d_in[3];
    const float4* W3 = (const float4*)d_in[4];
    float4* out = (float4*)d_out;

    const int N = in_sizes[0] / 4;  // T has N*4 index elements

    // R1's proven launch shape: 3x oversubscribed (8 resident blocks/SM,
    // 24 requested) — deeper chip-wide store queue, best measured DRAM%.
    const int threads = 256;
    const int blocks  = 148 * 24;
    time_encoder_gather_kernel<<<blocks, threads>>>(T, W0, W1, W2, W3, out, N);
}

// round 5
// speedup vs baseline: 1.1031x; 1.0178x over previous
#include <cuda_runtime.h>
#include <cuda_bf16.h>
#include <stdint.h>

// Warp-per-row gather. Lane j: table = j>>3, sub-float4 = j&7.
// Row output = [W0[t0] | W1[t1] | W2[t2] | W3[t3]] (4 x 32 floats = 128).
//
// Index dtype (int64 vs int32) detected in-kernel: each warp inspects the
// high 32-bit halves of the first 32 words of T. int64 little-endian with
// values < 366 -> all high halves zero; int32 -> odd words are random
// indices, P(all 32 zero) ~ 1e-50. One cached load + one ballot per warp.
__global__ void __launch_bounds__(256)
time_encoder_gather_kernel(const void* __restrict__ Tv,
                           const float4* __restrict__ W0,
                           const float4* __restrict__ W1,
                           const float4* __restrict__ W2,
                           const float4* __restrict__ W3,
                           float4* __restrict__ out,
                           int N) {
    const int lane = threadIdx.x & 31;
    const int dim  = lane >> 3;   // which table (0..3)
    const int sub  = lane & 7;    // which float4 within the 32-float slice

    // --- in-warp dtype detection ---
    const unsigned int* t32 = (const unsigned int*)Tv;
    unsigned int hi = __ldg(&t32[2 * lane + 1]);
    const bool is64 = (__ballot_sync(0xFFFFFFFFu, hi != 0u) == 0u);

    // Per-lane table base pointer (loop-invariant).
    const float4* W = (dim == 0) ? W0 : (dim == 1) ? W1 : (dim == 2) ? W2 : W3;

    const int warp   = (int)((blockIdx.x * blockDim.x + threadIdx.x) >> 5);
    const int nwarps = (int)((gridDim.x * blockDim.x) >> 5);

    const int*       T32 = (const int*)Tv;
    const long long* T64 = (const long long*)Tv;

    if (is64) {
        for (int row = warp; row < N; row += nwarps) {
            int idx = (int)__ldg(&T64[(size_t)row * 4 + dim]);
            float4 v = __ldg(&W[idx * 8 + sub]);      // tables ~57KB: L1-resident
            __stcs(&out[(size_t)row * 32 + lane], v); // write-once: evict-first
        }
    } else {
        for (int row = warp; row < N; row += nwarps) {
            int idx = __ldg(&T32[(size_t)row * 4 + dim]);
            float4 v = __ldg(&W[idx * 8 + sub]);
            __stcs(&out[(size_t)row * 32 + lane], v);
        }
    }
}

extern "C" void kernel_launch(void* const* d_in, const int* in_sizes, int n_in,
                              void* d_out, int out_size) {
    const void*   T  = d_in[0];
    const float4* W0 = (const float4*)d_in[1];
    const float4* W1 = (const float4*)d_in[2];
    const float4* W2 = (const float4*)d_in[3];
    const float4* W3 = (const float4*)d_in[4];
    float4* out = (float4*)d_out;

    const int N = in_sizes[0] / 4;  // T has N*4 index elements

    // Oversubscription sweep: 1184 blocks -> 68% DRAM, 3552 -> 74-76%.
    // Test the next point on the curve: 4 waves (148 SMs x 32 blocks).
    const int threads = 256;
    const int blocks  = 148 * 32;
    time_encoder_gather_kernel<<<blocks, threads>>>(T, W0, W1, W2, W3, out, N);
}

// round 6
// speedup vs baseline: 1.1275x; 1.0221x over previous
#include <cuda_runtime.h>
#include <cuda_bf16.h>
#include <stdint.h>

// Warp-per-row gather. Lane j: table = j>>3, sub-float4 = j&7.
// Row output = [W0[t0] | W1[t1] | W2[t2] | W3[t3]] (4 x 32 floats = 128).
//
// Index dtype (int64 vs int32) detected in-kernel: each warp inspects the
// high 32-bit halves of the first 32 words of T. int64 little-endian with
// values < 366 -> all high halves zero; int32 -> odd words are random
// indices, P(all 32 zero) ~ 1e-50. One cached load + one ballot per warp.
__global__ void __launch_bounds__(256)
time_encoder_gather_kernel(const void* __restrict__ Tv,
                           const float4* __restrict__ W0,
                           const float4* __restrict__ W1,
                           const float4* __restrict__ W2,
                           const float4* __restrict__ W3,
                           float4* __restrict__ out,
                           int N) {
    const int lane = threadIdx.x & 31;
    const int dim  = lane >> 3;   // which table (0..3)
    const int sub  = lane & 7;    // which float4 within the 32-float slice

    // --- in-warp dtype detection ---
    const unsigned int* t32 = (const unsigned int*)Tv;
    unsigned int hi = __ldg(&t32[2 * lane + 1]);
    const bool is64 = (__ballot_sync(0xFFFFFFFFu, hi != 0u) == 0u);

    // Per-lane table base pointer (loop-invariant).
    const float4* W = (dim == 0) ? W0 : (dim == 1) ? W1 : (dim == 2) ? W2 : W3;

    const int warp   = (int)((blockIdx.x * blockDim.x + threadIdx.x) >> 5);
    const int nwarps = (int)((gridDim.x * blockDim.x) >> 5);

    const int*       T32 = (const int*)Tv;
    const long long* T64 = (const long long*)Tv;

    if (is64) {
        for (int row = warp; row < N; row += nwarps) {
            int idx = (int)__ldg(&T64[(size_t)row * 4 + dim]);
            float4 v = __ldg(&W[idx * 8 + sub]);      // tables ~57KB: L1-resident
            __stcs(&out[(size_t)row * 32 + lane], v); // write-once: evict-first
        }
    } else {
        for (int row = warp; row < N; row += nwarps) {
            int idx = __ldg(&T32[(size_t)row * 4 + dim]);
            float4 v = __ldg(&W[idx * 8 + sub]);
            __stcs(&out[(size_t)row * 32 + lane], v);
        }
    }
}

extern "C" void kernel_launch(void* const* d_in, const int* in_sizes, int n_in,
                              void* d_out, int out_size) {
    const void*   T  = d_in[0];
    const float4* W0 = (const float4*)d_in[1];
    const float4* W1 = (const float4*)d_in[2];
    const float4* W2 = (const float4*)d_in[3];
    const float4* W3 = (const float4*)d_in[4];
    float4* out = (float4*)d_out;

    const int N = in_sizes[0] / 4;  // T has N*4 index elements

    // Oversubscription sweep: 1184 -> 68.4% DRAM, 3552 -> 74-76%, 4736 -> 76.0%.
    // Final sweep point: 6 waves (148 SMs x 48 blocks).
    const int threads = 256;
    const int blocks  = 148 * 48;
    time_encoder_gather_kernel<<<blocks, threads>>>(T, W0, W1, W2, W3, out, N);
}

// round 7
// speedup vs baseline: 1.1521x; 1.0218x over previous
#include <cuda_runtime.h>
#include <cuda_bf16.h>
#include <stdint.h>

// Warp-per-row gather. Lane j: table = j>>3, sub-float4 = j&7.
// Row output = [W0[t0] | W1[t1] | W2[t2] | W3[t3]] (4 x 32 floats = 128).
//
// Index dtype (int64 vs int32) detected in-kernel: each warp inspects the
// high 32-bit halves of the first 32 words of T. int64 little-endian with
// values < 366 -> all high halves zero; int32 -> odd words are random
// indices, P(all 32 zero) ~ 1e-50. One cached load + one ballot per warp.
__global__ void __launch_bounds__(256)
time_encoder_gather_kernel(const void* __restrict__ Tv,
                           const float4* __restrict__ W0,
                           const float4* __restrict__ W1,
                           const float4* __restrict__ W2,
                           const float4* __restrict__ W3,
                           float4* __restrict__ out,
                           int N) {
    const int lane = threadIdx.x & 31;
    const int dim  = lane >> 3;   // which table (0..3)
    const int sub  = lane & 7;    // which float4 within the 32-float slice

    // --- in-warp dtype detection ---
    const unsigned int* t32 = (const unsigned int*)Tv;
    unsigned int hi = __ldg(&t32[2 * lane + 1]);
    const bool is64 = (__ballot_sync(0xFFFFFFFFu, hi != 0u) == 0u);

    // Per-lane table base pointer (loop-invariant).
    const float4* W = (dim == 0) ? W0 : (dim == 1) ? W1 : (dim == 2) ? W2 : W3;

    const int warp   = (int)((blockIdx.x * blockDim.x + threadIdx.x) >> 5);
    const int nwarps = (int)((gridDim.x * blockDim.x) >> 5);

    const int*       T32 = (const int*)Tv;
    const long long* T64 = (const long long*)Tv;

    if (is64) {
        for (int row = warp; row < N; row += nwarps) {
            int idx = (int)__ldg(&T64[(size_t)row * 4 + dim]);
            float4 v = __ldg(&W[idx * 8 + sub]);      // tables ~57KB: L1-resident
            __stcs(&out[(size_t)row * 32 + lane], v); // write-once: evict-first
        }
    } else {
        for (int row = warp; row < N; row += nwarps) {
            int idx = __ldg(&T32[(size_t)row * 4 + dim]);
            float4 v = __ldg(&W[idx * 8 + sub]);
            __stcs(&out[(size_t)row * 32 + lane], v);
        }
    }
}

extern "C" void kernel_launch(void* const* d_in, const int* in_sizes, int n_in,
                              void* d_out, int out_size) {
    const void*   T  = d_in[0];
    const float4* W0 = (const float4*)d_in[1];
    const float4* W1 = (const float4*)d_in[2];
    const float4* W2 = (const float4*)d_in[3];
    const float4* W3 = (const float4*)d_in[4];
    float4* out = (float4*)d_out;

    const int N = in_sizes[0] / 4;  // T has N*4 index elements

    // Oversubscription sweep: 1184 -> 68.4%, 3552 -> 74-76%, 4736 -> 76.0%,
    // 7104 -> 77.9% DRAM (161.3us). Curve still rising: test 148 x 96.
    const int threads = 256;
    const int blocks  = 148 * 96;
    time_encoder_gather_kernel<<<blocks, threads>>>(T, W0, W1, W2, W3, out, N);
}

// round 8
// speedup vs baseline: 1.1667x; 1.0127x over previous
#include <cuda_runtime.h>
#include <cuda_bf16.h>
#include <stdint.h>

// Warp-per-row gather. Lane j: table = j>>3, sub-float4 = j&7.
// Row output = [W0[t0] | W1[t1] | W2[t2] | W3[t3]] (4 x 32 floats = 128).
//
// Index dtype (int64 vs int32) detected in-kernel: each warp inspects the
// high 32-bit halves of the first 32 words of T. int64 little-endian with
// values < 366 -> all high halves zero; int32 -> odd words are random
// indices, P(all 32 zero) ~ 1e-50. One cached load + one ballot per warp.
__global__ void __launch_bounds__(256)
time_encoder_gather_kernel(const void* __restrict__ Tv,
                           const float4* __restrict__ W0,
                           const float4* __restrict__ W1,
                           const float4* __restrict__ W2,
                           const float4* __restrict__ W3,
                           float4* __restrict__ out,
                           int N) {
    const int lane = threadIdx.x & 31;
    const int dim  = lane >> 3;   // which table (0..3)
    const int sub  = lane & 7;    // which float4 within the 32-float slice

    // --- in-warp dtype detection ---
    const unsigned int* t32 = (const unsigned int*)Tv;
    unsigned int hi = __ldg(&t32[2 * lane + 1]);
    const bool is64 = (__ballot_sync(0xFFFFFFFFu, hi != 0u) == 0u);

    // Per-lane table base pointer (loop-invariant).
    const float4* W = (dim == 0) ? W0 : (dim == 1) ? W1 : (dim == 2) ? W2 : W3;

    const int warp   = (int)((blockIdx.x * blockDim.x + threadIdx.x) >> 5);
    const int nwarps = (int)((gridDim.x * blockDim.x) >> 5);

    const int*       T32 = (const int*)Tv;
    const long long* T64 = (const long long*)Tv;

    if (is64) {
        for (int row = warp; row < N; row += nwarps) {
            int idx = (int)__ldg(&T64[(size_t)row * 4 + dim]);
            float4 v = __ldg(&W[idx * 8 + sub]);      // tables ~57KB: L1-resident
            __stcs(&out[(size_t)row * 32 + lane], v); // write-once: evict-first
        }
    } else {
        for (int row = warp; row < N; row += nwarps) {
            int idx = __ldg(&T32[(size_t)row * 4 + dim]);
            float4 v = __ldg(&W[idx * 8 + sub]);
            __stcs(&out[(size_t)row * 32 + lane], v);
        }
    }
}

extern "C" void kernel_launch(void* const* d_in, const int* in_sizes, int n_in,
                              void* d_out, int out_size) {
    const void*   T  = d_in[0];
    const float4* W0 = (const float4*)d_in[1];
    const float4* W1 = (const float4*)d_in[2];
    const float4* W2 = (const float4*)d_in[3];
    const float4* W3 = (const float4*)d_in[4];
    float4* out = (float4*)d_out;

    const int N = in_sizes[0] / 4;  // T has N*4 index elements

    // Oversubscription sweep: 1184 -> 68.4%, 3552 -> 74-76%, 4736 -> 76.0%,
    // 7104 -> 77.9%, 14208 -> 78.3% DRAM (160.4us). Final doubling: 148 x 192.
    const int threads = 256;
    const int blocks  = 148 * 192;
    time_encoder_gather_kernel<<<blocks, threads>>>(T, W0, W1, W2, W3, out, N);
}

// round 9
// speedup vs baseline: 1.1876x; 1.0179x over previous
#include <cuda_runtime.h>
#include <cuda_bf16.h>
#include <stdint.h>

// Warp-per-row gather. Lane j: table = j>>3, sub-float4 = j&7.
// Row output = [W0[t0] | W1[t1] | W2[t2] | W3[t3]] (4 x 32 floats = 128).
//
// Index dtype (int64 vs int32) detected in-kernel: each warp inspects the
// high 32-bit halves of the first 32 words of T. int64 little-endian with
// values < 366 -> all high halves zero; int32 -> odd words are random
// indices, P(all 32 zero) ~ 1e-50. One cached load + one ballot per warp.
__global__ void __launch_bounds__(256)
time_encoder_gather_kernel(const void* __restrict__ Tv,
                           const float4* __restrict__ W0,
                           const float4* __restrict__ W1,
                           const float4* __restrict__ W2,
                           const float4* __restrict__ W3,
                           float4* __restrict__ out,
                           int N) {
    const int lane = threadIdx.x & 31;
    const int dim  = lane >> 3;   // which table (0..3)
    const int sub  = lane & 7;    // which float4 within the 32-float slice

    // --- in-warp dtype detection ---
    const unsigned int* t32 = (const unsigned int*)Tv;
    unsigned int hi = __ldg(&t32[2 * lane + 1]);
    const bool is64 = (__ballot_sync(0xFFFFFFFFu, hi != 0u) == 0u);

    // Per-lane table base pointer (loop-invariant).
    const float4* W = (dim == 0) ? W0 : (dim == 1) ? W1 : (dim == 2) ? W2 : W3;

    const int warp   = (int)((blockIdx.x * blockDim.x + threadIdx.x) >> 5);
    const int nwarps = (int)((gridDim.x * blockDim.x) >> 5);

    const int*       T32 = (const int*)Tv;
    const long long* T64 = (const long long*)Tv;

    if (is64) {
        for (int row = warp; row < N; row += nwarps) {
            int idx = (int)__ldg(&T64[(size_t)row * 4 + dim]);
            float4 v = __ldg(&W[idx * 8 + sub]);      // tables ~57KB: L1-resident
            __stcs(&out[(size_t)row * 32 + lane], v); // write-once: evict-first
        }
    } else {
        for (int row = warp; row < N; row += nwarps) {
            int idx = __ldg(&T32[(size_t)row * 4 + dim]);
            float4 v = __ldg(&W[idx * 8 + sub]);
            __stcs(&out[(size_t)row * 32 + lane], v);
        }
    }
}

extern "C" void kernel_launch(void* const* d_in, const int* in_sizes, int n_in,
                              void* d_out, int out_size) {
    const void*   T  = d_in[0];
    const float4* W0 = (const float4*)d_in[1];
    const float4* W1 = (const float4*)d_in[2];
    const float4* W2 = (const float4*)d_in[3];
    const float4* W3 = (const float4*)d_in[4];
    float4* out = (float4*)d_out;

    const int N = in_sizes[0] / 4;  // T has N*4 index elements

    // Oversubscription sweep: 1184 -> 68.4%, 4736 -> 76.0%, 7104 -> 77.9%,
    // 14208 -> 78.3%, 28416 -> 79.1% DRAM (159.0us). Next doubling: 148 x 384.
    const int threads = 256;
    const int blocks  = 148 * 384;
    time_encoder_gather_kernel<<<blocks, threads>>>(T, W0, W1, W2, W3, out, N);
}